// round 1
// baseline (speedup 1.0000x reference)
#include <cuda_runtime.h>
#include <cuda_bf16.h>
#include <math.h>

// Problem constants
#define NB   2
#define HH   8
#define TT   1024
#define HID  64
#define NHB  (NB*HH)          // 16 sequences
#define D2   (2*HID)          // 128 feature dim after cos/sin expansion
#define EMB  (HH*HID)         // 512
#define LCH  128              // chunk length
#define NCH  (TT/LCH)         // 8 chunks
#define CTX_ELEMS (NB*HH*TT*HID)  // 1048576

// Scratch (device globals; no allocation allowed)
__device__ float g_S   [NHB*NCH*D2*HID];   // chunk sums   [b][c][d][m]  4MB
__device__ float g_P   [NHB*NCH*D2*HID];   // excl prefix  [b][c][d][m]  4MB
__device__ float g_sk  [NHB*NCH*D2];       // chunk k sums
__device__ float g_skP [NHB*NCH*D2];       // excl prefix of k sums
__device__ float g_attn[TT*NB*EMB];        // attn in (t, n, e) layout   4MB
__device__ float g_sinT[TT];
__device__ float g_cosT[TT];

// ---------------------------------------------------------------------------
// Kernel 0: sin/cos table (double precision, 1024 entries)
// ---------------------------------------------------------------------------
__global__ void sincos_init_kernel() {
    int t = blockIdx.x * blockDim.x + threadIdx.x;
    if (t < TT) {
        double ang = (3.14159265358979323846 / 2.0) * (double)(t + 1) / (double)TT;
        g_sinT[t] = (float)sin(ang);
        g_cosT[t] = (float)cos(ang);
    }
}

// ---------------------------------------------------------------------------
// Kernel A: per-(b,chunk) sums  S_c = K_^T V  (128x64),  sk_c = sum_t k_
// grid (16, 8), 256 threads, dyn smem = (128*128 + 128*64)*4 = 96KB
// ---------------------------------------------------------------------------
__global__ void chunk_sums_kernel(const float* __restrict__ k,
                                  const float* __restrict__ v) {
    extern __shared__ float sm[];
    float* sK = sm;                 // [t][d]  stride 128, 16384 floats
    float* sV = sm + LCH * D2;      // [t][m]  stride 64,   8192 floats

    const int b   = blockIdx.x;
    const int c   = blockIdx.y;
    const int tid = threadIdx.x;

    // load K_ (relu * sin/cos expansion)
    for (int i = tid; i < LCH * HID; i += 256) {
        int t  = i >> 6;
        int dd = i & 63;
        int tg = c * LCH + t;
        float kv = k[((b * TT) + tg) * HID + dd];
        kv = fmaxf(kv, 0.f);
        sK[t * D2 + dd]       = kv * g_sinT[tg];
        sK[t * D2 + HID + dd] = kv * g_cosT[tg];
    }
    // load V (vr[b,t,m] = v_flat[(t*NHB + b)*HID + m])
    for (int i = tid; i < LCH * HID; i += 256) {
        int t = i >> 6;
        int m = i & 63;
        int tg = c * LCH + t;
        sV[i] = v[(tg * NHB + b) * HID + m];
    }
    __syncthreads();

    // S[d][m] = sum_t K_[t][d] * V[t][m]
    const int m  = tid & 63;
    const int d0 = tid >> 6;     // 0..3, each owns 32 consecutive d
    float4 acc4[8];
#pragma unroll
    for (int g = 0; g < 8; ++g) acc4[g] = make_float4(0.f, 0.f, 0.f, 0.f);

    const float4* sK4 = reinterpret_cast<const float4*>(sK);
    for (int t = 0; t < LCH; ++t) {
        float vv = sV[t * HID + m];
        const float4* row = sK4 + t * (D2 / 4) + d0 * 8;
#pragma unroll
        for (int g = 0; g < 8; ++g) {
            float4 kk = row[g];
            acc4[g].x += kk.x * vv;
            acc4[g].y += kk.y * vv;
            acc4[g].z += kk.z * vv;
            acc4[g].w += kk.w * vv;
        }
    }
    float* Sout = &g_S[(size_t)((b * NCH + c)) * (D2 * HID)];
#pragma unroll
    for (int g = 0; g < 8; ++g) {
        int dbase = d0 * 32 + g * 4;
        Sout[(dbase + 0) * HID + m] = acc4[g].x;
        Sout[(dbase + 1) * HID + m] = acc4[g].y;
        Sout[(dbase + 2) * HID + m] = acc4[g].z;
        Sout[(dbase + 3) * HID + m] = acc4[g].w;
    }

    if (tid < D2) {
        float s = 0.f;
        for (int t = 0; t < LCH; ++t) s += sK[t * D2 + tid];
        g_sk[(b * NCH + c) * D2 + tid] = s;
    }
}

// ---------------------------------------------------------------------------
// Kernel B: exclusive prefix over chunks (per b)
// grid 16, 256 threads
// ---------------------------------------------------------------------------
__global__ void prefix_kernel() {
    const int b   = blockIdx.x;
    const int tid = threadIdx.x;
    for (int i = tid; i < D2 * HID; i += 256) {
        float run = 0.f;
#pragma unroll
        for (int c = 0; c < NCH; ++c) {
            size_t idx = (size_t)(b * NCH + c) * (D2 * HID) + i;
            g_P[idx] = run;
            run += g_S[idx];
        }
    }
    if (tid < D2) {
        float run = 0.f;
#pragma unroll
        for (int c = 0; c < NCH; ++c) {
            int idx = (b * NCH + c) * D2 + tid;
            g_skP[idx] = run;
            run += g_sk[idx];
        }
    }
}

// ---------------------------------------------------------------------------
// Kernel C: per-(b,chunk) output
//   O   = Q_ @ P_c + causal(Q_ K_^T) @ V
//   den = Q_ . skP_c + rowsum(causal scores)
//   attn = O / max(den, eps)   written to (t, n, h*64+m) layout
// grid (16, 8), 256 threads, dyn smem = 229888 B
// ---------------------------------------------------------------------------
__global__ void chunk_out_kernel(const float* __restrict__ q,
                                 const float* __restrict__ k,
                                 const float* __restrict__ v) {
    extern __shared__ float sm[];
    float* sQ = sm;                                   // [t][d]  stride 128
    float* sK = sm + LCH * D2;                        // [tp][d] stride 129 (pad)
    float* sV = sm + LCH * D2 + LCH * 129;            // [tp][m] stride 64
    float* sS = sm + LCH * D2 + LCH * 129 + LCH * HID;// [t][tp] stride 128
    __shared__ float sDen[LCH];

    const int b   = blockIdx.x;
    const int c   = blockIdx.y;
    const int tid = threadIdx.x;
    const int lane = tid & 31;
    const int wid  = tid >> 5;

    // load Q_, K_
    for (int i = tid; i < LCH * HID; i += 256) {
        int t  = i >> 6;
        int dd = i & 63;
        int tg = c * LCH + t;
        float sv = g_sinT[tg], cv = g_cosT[tg];
        float qv = fmaxf(q[((b * TT) + tg) * HID + dd], 0.f);
        float kv = fmaxf(k[((b * TT) + tg) * HID + dd], 0.f);
        sQ[t * D2 + dd]        = qv * sv;
        sQ[t * D2 + HID + dd]  = qv * cv;
        sK[t * 129 + dd]       = kv * sv;
        sK[t * 129 + HID + dd] = kv * cv;
    }
    for (int i = tid; i < LCH * HID; i += 256) {
        int t = i >> 6;
        int m = i & 63;
        int tg = c * LCH + t;
        sV[i] = v[(tg * NHB + b) * HID + m];
    }
    __syncthreads();

    // scores: warp 'wid' covers t in [wid*16, wid*16+16), lane -> tp (+32 strides)
#pragma unroll
    for (int g = 0; g < 4; ++g) {
        int t0 = wid * 16 + g * 4;
        float acc[4][4];
#pragma unroll
        for (int i = 0; i < 4; ++i)
#pragma unroll
            for (int j = 0; j < 4; ++j) acc[i][j] = 0.f;

        for (int d = 0; d < D2; ++d) {
            float q0 = sQ[(t0 + 0) * D2 + d];
            float q1 = sQ[(t0 + 1) * D2 + d];
            float q2 = sQ[(t0 + 2) * D2 + d];
            float q3 = sQ[(t0 + 3) * D2 + d];
            float k0 = sK[(lane +  0) * 129 + d];
            float k1 = sK[(lane + 32) * 129 + d];
            float k2 = sK[(lane + 64) * 129 + d];
            float k3 = sK[(lane + 96) * 129 + d];
            acc[0][0] += q0 * k0; acc[0][1] += q0 * k1; acc[0][2] += q0 * k2; acc[0][3] += q0 * k3;
            acc[1][0] += q1 * k0; acc[1][1] += q1 * k1; acc[1][2] += q1 * k2; acc[1][3] += q1 * k3;
            acc[2][0] += q2 * k0; acc[2][1] += q2 * k1; acc[2][2] += q2 * k2; acc[2][3] += q2 * k3;
            acc[3][0] += q3 * k0; acc[3][1] += q3 * k1; acc[3][2] += q3 * k2; acc[3][3] += q3 * k3;
        }
#pragma unroll
        for (int i = 0; i < 4; ++i)
#pragma unroll
            for (int j = 0; j < 4; ++j) {
                int t  = t0 + i;
                int tp = lane + 32 * j;
                sS[t * LCH + tp] = (tp <= t) ? acc[i][j] : 0.f;
            }
    }
    __syncthreads();

    // denom: warp 'wid' handles 16 rows, shuffle-reduce over 128 lanes*4
    {
        const float* skp = &g_skP[(b * NCH + c) * D2];
        for (int tt = 0; tt < 16; ++tt) {
            int t = wid * 16 + tt;
            float p = 0.f;
#pragma unroll
            for (int x = 0; x < 4; ++x) {
                int d = lane + 32 * x;
                p += sQ[t * D2 + d] * skp[d];
                p += sS[t * LCH + d];   // rowsum of masked scores
            }
#pragma unroll
            for (int o = 16; o > 0; o >>= 1) p += __shfl_xor_sync(0xFFFFFFFFu, p, o);
            if (lane == 0) sDen[t] = fmaxf(p, 1e-6f);
        }
    }
    __syncthreads();

    // O[t][m]: thread owns m = tid&63, t = tg0*32 + j
    {
        const int m   = tid & 63;
        const int tg0 = tid >> 6;   // 0..3
        float acc[32];
#pragma unroll
        for (int j = 0; j < 32; ++j) acc[j] = 0.f;

        const float* Pp = &g_P[(size_t)(b * NCH + c) * (D2 * HID)];
        for (int d = 0; d < D2; ++d) {
            float pv = Pp[d * HID + m];
#pragma unroll
            for (int j = 0; j < 32; ++j)
                acc[j] += sQ[(tg0 * 32 + j) * D2 + d] * pv;
        }
        for (int tp = 0; tp < LCH; ++tp) {
            float vv = sV[tp * HID + m];
#pragma unroll
            for (int j = 0; j < 32; ++j)
                acc[j] += sS[(tg0 * 32 + j) * LCH + tp] * vv;
        }
        const int n = b >> 3;
        const int h = b & 7;
#pragma unroll
        for (int j = 0; j < 32; ++j) {
            int t  = tg0 * 32 + j;
            int tg = c * LCH + t;
            g_attn[((size_t)tg * NB + n) * EMB + h * HID + m] = acc[j] / sDen[t];
        }
    }
}

// ---------------------------------------------------------------------------
// Kernel D: out = attn @ W^T + b, scattered to context (N,H,T,HID)
// grid (32, 8), 256 threads, tiles 64x64, k-tile 32, 4x4 per thread
// ---------------------------------------------------------------------------
__global__ void outproj_kernel(const float* __restrict__ W,
                               const float* __restrict__ bias,
                               float* __restrict__ out) {
    __shared__ float sA[64 * 33];
    __shared__ float sB[64 * 33];

    const int tid = threadIdx.x;
    const int rb = blockIdx.x * 64;   // attn row base (0..2047)
    const int nb = blockIdx.y * 64;   // out col base  (0..511)
    const int tx = tid & 15;
    const int ty = tid >> 4;

    float acc[4][4];
#pragma unroll
    for (int i = 0; i < 4; ++i)
#pragma unroll
        for (int j = 0; j < 4; ++j) acc[i][j] = 0.f;

    for (int k0 = 0; k0 < EMB; k0 += 32) {
        for (int i = tid; i < 64 * 32; i += 256) {
            int r  = i >> 5;
            int cc = i & 31;
            sA[r * 33 + cc] = g_attn[(size_t)(rb + r) * EMB + k0 + cc];
            sB[r * 33 + cc] = W[(size_t)(nb + r) * EMB + k0 + cc];
        }
        __syncthreads();
#pragma unroll
        for (int kk = 0; kk < 32; ++kk) {
            float a[4], bb[4];
#pragma unroll
            for (int i = 0; i < 4; ++i) a[i]  = sA[(ty * 4 + i) * 33 + kk];
#pragma unroll
            for (int j = 0; j < 4; ++j) bb[j] = sB[(tx * 4 + j) * 33 + kk];
#pragma unroll
            for (int i = 0; i < 4; ++i)
#pragma unroll
                for (int j = 0; j < 4; ++j) acc[i][j] += a[i] * bb[j];
        }
        __syncthreads();
    }

#pragma unroll
    for (int i = 0; i < 4; ++i) {
        int r = rb + ty * 4 + i;
        int t = r >> 1;
        int n = r & 1;
#pragma unroll
        for (int j = 0; j < 4; ++j) {
            int eo = nb + tx * 4 + j;
            int h  = eo >> 6;
            int d  = eo & 63;
            out[(((size_t)(n * HH + h) * TT) + t) * HID + d] = acc[i][j] + bias[eo];
        }
    }
}

// ---------------------------------------------------------------------------
// Launch
// ---------------------------------------------------------------------------
extern "C" void kernel_launch(void* const* d_in, const int* in_sizes, int n_in,
                              void* d_out, int out_size) {
    const float* q    = (const float*)d_in[0];
    const float* k    = (const float*)d_in[1];
    const float* v    = (const float*)d_in[2];
    const float* W    = (const float*)d_in[3];
    const float* bias = (const float*)d_in[4];
    float* out = (float*)d_out;

    // opt-in dynamic smem (idempotent, capture-safe: not stream-ordered)
    cudaFuncSetAttribute(chunk_sums_kernel,
                         cudaFuncAttributeMaxDynamicSharedMemorySize, 98304);
    cudaFuncSetAttribute(chunk_out_kernel,
                         cudaFuncAttributeMaxDynamicSharedMemorySize, 229888);

    // probs output (zeros), if the harness output includes it after context
    if (out_size > CTX_ELEMS) {
        cudaMemsetAsync(out + CTX_ELEMS, 0,
                        (size_t)(out_size - CTX_ELEMS) * sizeof(float), 0);
    }

    sincos_init_kernel<<<4, 256>>>();
    chunk_sums_kernel<<<dim3(NHB, NCH), 256, 98304>>>(k, v);
    prefix_kernel<<<NHB, 256>>>();
    chunk_out_kernel<<<dim3(NHB, NCH), 256, 229888>>>(q, k, v);
    outproj_kernel<<<dim3(32, 8), 256>>>(W, bias, out);
}

// round 3
// speedup vs baseline: 1.8370x; 1.8370x over previous
#include <cuda_runtime.h>
#include <cuda_bf16.h>
#include <math.h>

// Problem constants
#define NB   2
#define HH   8
#define TT   1024
#define HID  64
#define NHB  (NB*HH)          // 16 sequences
#define D2   (2*HID)          // 128 feature dim after cos/sin expansion
#define EMB  (HH*HID)         // 512
#define LCH  64               // chunk length
#define NCH  (TT/LCH)         // 16 chunks
#define CTX_ELEMS (NB*HH*TT*HID)  // 1048576

typedef unsigned long long u64t;

__device__ __forceinline__ u64t pack2(float lo, float hi) {
    u64t r; asm("mov.b64 %0, {%1, %2};" : "=l"(r) : "f"(lo), "f"(hi)); return r;
}
__device__ __forceinline__ float2 unpack2(u64t p) {
    float2 r; asm("mov.b64 {%0, %1}, %2;" : "=f"(r.x), "=f"(r.y) : "l"(p)); return r;
}
__device__ __forceinline__ void fma2(u64t& d, u64t a, u64t b) {
    asm("fma.rn.f32x2 %0, %1, %2, %0;" : "+l"(d) : "l"(a), "l"(b));
}

// Scratch (device globals; no allocation allowed)
__device__ float g_S   [NHB*NCH*D2*HID];   // chunk sums   [b][c][d][m]  8MB
__device__ float g_P   [NHB*NCH*D2*HID];   // excl prefix  [b][c][d][m]  8MB
__device__ float g_sk  [NHB*NCH*D2];       // chunk k sums
__device__ float g_skP [NHB*NCH*D2];       // excl prefix of k sums
__device__ float g_attn[TT*NB*EMB];        // attn in (t, n, e) layout   4MB
__device__ float g_sinT[TT];
__device__ float g_cosT[TT];

// ---------------------------------------------------------------------------
// Kernel 0: sin/cos table (double precision, 1024 entries)
// ---------------------------------------------------------------------------
__global__ void sincos_init_kernel() {
    int t = blockIdx.x * blockDim.x + threadIdx.x;
    if (t < TT) {
        double ang = (3.14159265358979323846 / 2.0) * (double)(t + 1) / (double)TT;
        g_sinT[t] = (float)sin(ang);
        g_cosT[t] = (float)cos(ang);
    }
}

// ---------------------------------------------------------------------------
// Kernel A: per-(b,chunk) sums  S_c = K_^T V  (128x64),  sk_c = sum_t k_
// grid (16, 16), 256 threads, dyn smem = 49152 B, 4 CTAs/SM
// ---------------------------------------------------------------------------
__global__ __launch_bounds__(256) void chunk_sums_kernel(const float* __restrict__ k,
                                                         const float* __restrict__ v) {
    extern __shared__ float sm[];
    float* sK = sm;              // [64][128]
    float* sV = sm + LCH * D2;   // [64][64]
    const int b = blockIdx.x, c = blockIdx.y, tid = threadIdx.x;

    // load K_ (relu * sin/cos expansion), float4 coalesced
    const float4* kg = reinterpret_cast<const float4*>(k + ((size_t)b * TT + c * LCH) * HID);
    for (int i = tid; i < LCH * 16; i += 256) {
        int t = i >> 4, c4 = i & 15;
        int tg = c * LCH + t;
        float sv = g_sinT[tg], cv = g_cosT[tg];
        float4 kv = kg[i];
        float x = fmaxf(kv.x, 0.f), y = fmaxf(kv.y, 0.f);
        float z = fmaxf(kv.z, 0.f), wv = fmaxf(kv.w, 0.f);
        float* row = sK + t * D2 + c4 * 4;
        row[0]  = x * sv; row[1]  = y * sv; row[2]  = z * sv; row[3]  = wv * sv;
        row[64] = x * cv; row[65] = y * cv; row[66] = z * cv; row[67] = wv * cv;
    }
    // load V (vr[b,t,m] = v_flat[(t*NHB + b)*HID + m])
    const float4* vg = reinterpret_cast<const float4*>(v);
    float4* sV4w = reinterpret_cast<float4*>(sV);
    for (int i = tid; i < LCH * 16; i += 256) {
        int t = i >> 4, c4 = i & 15;
        sV4w[t * 16 + c4] = vg[((size_t)(c * LCH + t) * NHB + b) * 16 + c4];
    }
    __syncthreads();

    // S[d][m] = sum_t K_[t][d] * V[t][m]; thread tile 8 d x 4 m
    const int tx = tid & 15, ty = tid >> 4;
    const int d0 = ty * 8, m0 = tx * 4;
    u64t acc[8][2];
#pragma unroll
    for (int i = 0; i < 8; ++i) { acc[i][0] = pack2(0.f, 0.f); acc[i][1] = pack2(0.f, 0.f); }

    const float4* sK4 = reinterpret_cast<const float4*>(sK);
    const float4* sV4 = reinterpret_cast<const float4*>(sV);
    for (int t = 0; t < LCH; ++t) {
        float4 a0 = sK4[t * 32 + ty * 2];
        float4 a1 = sK4[t * 32 + ty * 2 + 1];
        float4 bv = sV4[t * 16 + tx];
        u64t b01 = pack2(bv.x, bv.y), b23 = pack2(bv.z, bv.w);
        float av[8] = {a0.x, a0.y, a0.z, a0.w, a1.x, a1.y, a1.z, a1.w};
#pragma unroll
        for (int i = 0; i < 8; ++i) {
            u64t ad = pack2(av[i], av[i]);
            fma2(acc[i][0], ad, b01);
            fma2(acc[i][1], ad, b23);
        }
    }
    float* Sout = g_S + (size_t)(b * NCH + c) * (D2 * HID);
#pragma unroll
    for (int i = 0; i < 8; ++i) {
        float2 p0 = unpack2(acc[i][0]);
        float2 p1 = unpack2(acc[i][1]);
        *reinterpret_cast<float4*>(Sout + (d0 + i) * HID + m0) =
            make_float4(p0.x, p0.y, p1.x, p1.y);
    }

    if (tid < D2) {
        float s = 0.f;
        for (int t = 0; t < LCH; ++t) s += sK[t * D2 + tid];
        g_sk[(b * NCH + c) * D2 + tid] = s;
    }
}

// ---------------------------------------------------------------------------
// Kernel B: exclusive prefix over 16 chunks (per b), grid (16, 16)
// ---------------------------------------------------------------------------
__global__ __launch_bounds__(256) void prefix_kernel() {
    const int b = blockIdx.x, s = blockIdx.y, tid = threadIdx.x;
    size_t eoff = (size_t)s * 512 + tid * 2;
    float r0 = 0.f, r1 = 0.f;
#pragma unroll
    for (int c = 0; c < NCH; ++c) {
        size_t base = (size_t)(b * NCH + c) * (D2 * HID) + eoff;
        float2 sv = *reinterpret_cast<const float2*>(&g_S[base]);
        *reinterpret_cast<float2*>(&g_P[base]) = make_float2(r0, r1);
        r0 += sv.x; r1 += sv.y;
    }
    if (s == 0 && tid < D2) {
        float run = 0.f;
#pragma unroll
        for (int c = 0; c < NCH; ++c) {
            int idx = (b * NCH + c) * D2 + tid;
            g_skP[idx] = run;
            run += g_sk[idx];
        }
    }
}

// ---------------------------------------------------------------------------
// Kernel C: per-(b,chunk) output, L=64
//   O   = Q_ @ P_c + causal(Q_ K_^T) @ V
//   den = Q_ . skP_c + rowsum(causal scores)
// grid (16, 16), 256 threads, dyn smem = 101120 B, 2 CTAs/SM
// ---------------------------------------------------------------------------
__global__ __launch_bounds__(256, 2) void chunk_out_kernel(const float* __restrict__ q,
                                                           const float* __restrict__ k,
                                                           const float* __restrict__ v) {
    extern __shared__ float sm[];
    float* sQ   = sm;                         // [64][128]          8192 f
    float* sKP  = sm + 8192;                  // K [64][132] / P [128][68]  8704 f
    float* sV   = sm + 8192 + 8704;           // [64][64]           4096 f
    float* sS   = sm + 8192 + 8704 + 4096;    // [64][64]           4096 f
    float* sSkp = sm + 25088;                 // [128]
    float* sDen = sm + 25216;                 // [64]

    const int b = blockIdx.x, c = blockIdx.y, tid = threadIdx.x;
    const int lane = tid & 31, w = tid >> 5;

    // ---- load & expand Q_, K_; load V, skP ----
    const float4* qg = reinterpret_cast<const float4*>(q + ((size_t)b * TT + c * LCH) * HID);
    const float4* kg = reinterpret_cast<const float4*>(k + ((size_t)b * TT + c * LCH) * HID);
    for (int i = tid; i < LCH * 16; i += 256) {
        int t = i >> 4, c4 = i & 15;
        int tg = c * LCH + t;
        float sv = g_sinT[tg], cv = g_cosT[tg];
        float4 qv = qg[i];
        float qx = fmaxf(qv.x, 0.f), qy = fmaxf(qv.y, 0.f);
        float qz = fmaxf(qv.z, 0.f), qw = fmaxf(qv.w, 0.f);
        float* qrow = sQ + t * D2 + c4 * 4;
        qrow[0]  = qx * sv; qrow[1]  = qy * sv; qrow[2]  = qz * sv; qrow[3]  = qw * sv;
        qrow[64] = qx * cv; qrow[65] = qy * cv; qrow[66] = qz * cv; qrow[67] = qw * cv;
        float4 kv = kg[i];
        float kx = fmaxf(kv.x, 0.f), ky = fmaxf(kv.y, 0.f);
        float kz = fmaxf(kv.z, 0.f), kw = fmaxf(kv.w, 0.f);
        float* krow = sKP + t * 132 + c4 * 4;
        krow[0]  = kx * sv; krow[1]  = ky * sv; krow[2]  = kz * sv; krow[3]  = kw * sv;
        krow[64] = kx * cv; krow[65] = ky * cv; krow[66] = kz * cv; krow[67] = kw * cv;
    }
    const float4* vg = reinterpret_cast<const float4*>(v);
    float4* sV4w = reinterpret_cast<float4*>(sV);
    for (int i = tid; i < LCH * 16; i += 256) {
        int t = i >> 4, c4 = i & 15;
        sV4w[t * 16 + c4] = vg[((size_t)(c * LCH + t) * NHB + b) * 16 + c4];
    }
    if (tid < D2) sSkp[tid] = g_skP[(b * NCH + c) * D2 + tid];
    __syncthreads();

    // ---- scores: warp w owns rows [8w, 8w+8); lane -> cols {lane, lane+32} ----
    {
        const float4* sQ4 = reinterpret_cast<const float4*>(sQ);
        const float4* sK4 = reinterpret_cast<const float4*>(sKP);  // stride 33 f4
        const int r0 = w * 8;
        float acc0[8] = {0, 0, 0, 0, 0, 0, 0, 0};
        float acc1[8] = {0, 0, 0, 0, 0, 0, 0, 0};
        if (w < 4) {   // rows < 32: upper column block fully masked -> skip
            for (int d4 = 0; d4 < 32; ++d4) {
                float4 k0 = sK4[lane * 33 + d4];
#pragma unroll
                for (int i = 0; i < 8; ++i) {
                    float4 qv = sQ4[(r0 + i) * 32 + d4];
                    acc0[i] = fmaf(qv.x, k0.x, acc0[i]);
                    acc0[i] = fmaf(qv.y, k0.y, acc0[i]);
                    acc0[i] = fmaf(qv.z, k0.z, acc0[i]);
                    acc0[i] = fmaf(qv.w, k0.w, acc0[i]);
                }
            }
        } else {
            for (int d4 = 0; d4 < 32; ++d4) {
                float4 k0 = sK4[lane * 33 + d4];
                float4 k1 = sK4[(lane + 32) * 33 + d4];
#pragma unroll
                for (int i = 0; i < 8; ++i) {
                    float4 qv = sQ4[(r0 + i) * 32 + d4];
                    acc0[i] = fmaf(qv.x, k0.x, acc0[i]);
                    acc0[i] = fmaf(qv.y, k0.y, acc0[i]);
                    acc0[i] = fmaf(qv.z, k0.z, acc0[i]);
                    acc0[i] = fmaf(qv.w, k0.w, acc0[i]);
                    acc1[i] = fmaf(qv.x, k1.x, acc1[i]);
                    acc1[i] = fmaf(qv.y, k1.y, acc1[i]);
                    acc1[i] = fmaf(qv.z, k1.z, acc1[i]);
                    acc1[i] = fmaf(qv.w, k1.w, acc1[i]);
                }
            }
        }
        // mask, store scores, denominator = Q.skP + rowsum
#pragma unroll
        for (int i = 0; i < 8; ++i) {
            int r = r0 + i;
            float qd = sQ[r * D2 + lane]      * sSkp[lane]
                     + sQ[r * D2 + lane + 32] * sSkp[lane + 32]
                     + sQ[r * D2 + lane + 64] * sSkp[lane + 64]
                     + sQ[r * D2 + lane + 96] * sSkp[lane + 96];
            float v0 = (lane <= r)      ? acc0[i] : 0.f;
            float v1 = (lane + 32 <= r) ? acc1[i] : 0.f;
            sS[r * LCH + lane]      = v0;
            sS[r * LCH + lane + 32] = v1;
            float p = v0 + v1 + qd;
#pragma unroll
            for (int o = 16; o > 0; o >>= 1) p += __shfl_xor_sync(0xFFFFFFFFu, p, o);
            if (lane == 0) sDen[r] = fmaxf(p, 1e-6f);
        }
    }
    __syncthreads();

    // ---- stage P into sKP (K no longer needed) ----
    {
        const float4* Pg = reinterpret_cast<const float4*>(g_P + (size_t)(b * NCH + c) * (D2 * HID));
        float4* sP4 = reinterpret_cast<float4*>(sKP);
        for (int i = tid; i < 2048; i += 256) {
            int row = i >> 4, c4 = i & 15;
            sP4[row * 17 + c4] = Pg[i];
        }
    }
    __syncthreads();

    // ---- O = Q@P + S@V, 4x4 per thread, f32x2 ----
    {
        const int tx = tid & 15, ty = tid >> 4;
        const int r0 = ty * 4, m0 = tx * 4;
        const float4* sQ4 = reinterpret_cast<const float4*>(sQ);
        const float4* sP4 = reinterpret_cast<const float4*>(sKP);
        const float4* sS4 = reinterpret_cast<const float4*>(sS);
        const float4* sV4 = reinterpret_cast<const float4*>(sV);
        u64t acc[4][2];
#pragma unroll
        for (int i = 0; i < 4; ++i) { acc[i][0] = pack2(0.f, 0.f); acc[i][1] = pack2(0.f, 0.f); }

        for (int d4 = 0; d4 < 32; ++d4) {
            float4 a[4];
#pragma unroll
            for (int i = 0; i < 4; ++i) a[i] = sQ4[(r0 + i) * 32 + d4];
            float4 b0 = sP4[(4 * d4 + 0) * 17 + tx];
            float4 b1 = sP4[(4 * d4 + 1) * 17 + tx];
            float4 b2 = sP4[(4 * d4 + 2) * 17 + tx];
            float4 b3 = sP4[(4 * d4 + 3) * 17 + tx];
            u64t b0l = pack2(b0.x, b0.y), b0h = pack2(b0.z, b0.w);
            u64t b1l = pack2(b1.x, b1.y), b1h = pack2(b1.z, b1.w);
            u64t b2l = pack2(b2.x, b2.y), b2h = pack2(b2.z, b2.w);
            u64t b3l = pack2(b3.x, b3.y), b3h = pack2(b3.z, b3.w);
#pragma unroll
            for (int i = 0; i < 4; ++i) {
                u64t ax = pack2(a[i].x, a[i].x);
                fma2(acc[i][0], ax, b0l); fma2(acc[i][1], ax, b0h);
                u64t ay = pack2(a[i].y, a[i].y);
                fma2(acc[i][0], ay, b1l); fma2(acc[i][1], ay, b1h);
                u64t az = pack2(a[i].z, a[i].z);
                fma2(acc[i][0], az, b2l); fma2(acc[i][1], az, b2h);
                u64t aw = pack2(a[i].w, a[i].w);
                fma2(acc[i][0], aw, b3l); fma2(acc[i][1], aw, b3h);
            }
        }
        for (int tp4 = 0; tp4 < 16; ++tp4) {
            float4 a[4];
#pragma unroll
            for (int i = 0; i < 4; ++i) a[i] = sS4[(r0 + i) * 16 + tp4];
            float4 b0 = sV4[(4 * tp4 + 0) * 16 + tx];
            float4 b1 = sV4[(4 * tp4 + 1) * 16 + tx];
            float4 b2 = sV4[(4 * tp4 + 2) * 16 + tx];
            float4 b3 = sV4[(4 * tp4 + 3) * 16 + tx];
            u64t b0l = pack2(b0.x, b0.y), b0h = pack2(b0.z, b0.w);
            u64t b1l = pack2(b1.x, b1.y), b1h = pack2(b1.z, b1.w);
            u64t b2l = pack2(b2.x, b2.y), b2h = pack2(b2.z, b2.w);
            u64t b3l = pack2(b3.x, b3.y), b3h = pack2(b3.z, b3.w);
#pragma unroll
            for (int i = 0; i < 4; ++i) {
                u64t ax = pack2(a[i].x, a[i].x);
                fma2(acc[i][0], ax, b0l); fma2(acc[i][1], ax, b0h);
                u64t ay = pack2(a[i].y, a[i].y);
                fma2(acc[i][0], ay, b1l); fma2(acc[i][1], ay, b1h);
                u64t az = pack2(a[i].z, a[i].z);
                fma2(acc[i][0], az, b2l); fma2(acc[i][1], az, b2h);
                u64t aw = pack2(a[i].w, a[i].w);
                fma2(acc[i][0], aw, b3l); fma2(acc[i][1], aw, b3h);
            }
        }

        const int n = b >> 3, h = b & 7;
#pragma unroll
        for (int i = 0; i < 4; ++i) {
            int r = r0 + i;
            float inv = 1.0f / sDen[r];
            float2 p0 = unpack2(acc[i][0]);
            float2 p1 = unpack2(acc[i][1]);
            int tg = c * LCH + r;
            *reinterpret_cast<float4*>(g_attn + ((size_t)tg * NB + n) * EMB + h * HID + m0) =
                make_float4(p0.x * inv, p0.y * inv, p1.x * inv, p1.y * inv);
        }
    }
}

// ---------------------------------------------------------------------------
// Kernel D: out = attn @ W^T + b, scattered to context (N,H,T,HID)
// grid (16, 8) = 128 CTAs, 256 threads, 128x64 tiles, k-tile 32, 8x4/thread
// transposed smem (A,B stored [kk][row]) + f32x2
// ---------------------------------------------------------------------------
#define SB_STRIDE 72   // EVEN stride (72 floats = 288 B, 16B-aligned rows)
__global__ __launch_bounds__(256) void outproj_kernel(const float* __restrict__ W,
                                                      const float* __restrict__ bias,
                                                      float* __restrict__ out) {
    __shared__ float sA[32 * 137];        // [kk][r], r=0..127, pad 137 (scalar reads only)
    __shared__ float sB[32 * SB_STRIDE];  // [kk][n], n=0..63

    const int tid = threadIdx.x;
    const int rb = blockIdx.x * 128;
    const int nb = blockIdx.y * 64;
    const int tx = tid & 15, ty = tid >> 4;
    const int r0 = ty * 8, m0 = tx * 4;

    u64t acc[8][2];
#pragma unroll
    for (int i = 0; i < 8; ++i) { acc[i][0] = pack2(0.f, 0.f); acc[i][1] = pack2(0.f, 0.f); }

    const float4* Ag = reinterpret_cast<const float4*>(g_attn);
    const float4* Wg = reinterpret_cast<const float4*>(W);

    for (int k0 = 0; k0 < EMB; k0 += 32) {
        for (int i = tid; i < 1024; i += 256) {   // A tile: 128 r x 8 f4
            int r = i >> 3, k4 = i & 7;
            float4 a = Ag[(size_t)(rb + r) * (EMB / 4) + (k0 >> 2) + k4];
            sA[(k4 * 4 + 0) * 137 + r] = a.x;
            sA[(k4 * 4 + 1) * 137 + r] = a.y;
            sA[(k4 * 4 + 2) * 137 + r] = a.z;
            sA[(k4 * 4 + 3) * 137 + r] = a.w;
        }
        for (int i = tid; i < 512; i += 256) {    // B tile: 64 n x 8 f4
            int n = i >> 3, k4 = i & 7;
            float4 wv = Wg[(size_t)(nb + n) * (EMB / 4) + (k0 >> 2) + k4];
            sB[(k4 * 4 + 0) * SB_STRIDE + n] = wv.x;
            sB[(k4 * 4 + 1) * SB_STRIDE + n] = wv.y;
            sB[(k4 * 4 + 2) * SB_STRIDE + n] = wv.z;
            sB[(k4 * 4 + 3) * SB_STRIDE + n] = wv.w;
        }
        __syncthreads();
#pragma unroll 8
        for (int kk = 0; kk < 32; ++kk) {
            float2 bl = *reinterpret_cast<const float2*>(&sB[kk * SB_STRIDE + m0]);
            float2 bh = *reinterpret_cast<const float2*>(&sB[kk * SB_STRIDE + m0 + 2]);
            u64t b0 = pack2(bl.x, bl.y), b1 = pack2(bh.x, bh.y);
            const float* arow = &sA[kk * 137 + r0];
#pragma unroll
            for (int i = 0; i < 8; ++i) {
                float a = arow[i];
                u64t ad = pack2(a, a);
                fma2(acc[i][0], ad, b0);
                fma2(acc[i][1], ad, b1);
            }
        }
        __syncthreads();
    }

    float4 bv = *reinterpret_cast<const float4*>(&bias[nb + m0]);
    const int h = nb >> 6;   // nb multiple of 64, m0 < 64
#pragma unroll
    for (int i = 0; i < 8; ++i) {
        int r = rb + r0 + i;
        int t = r >> 1, n = r & 1;
        float2 p0 = unpack2(acc[i][0]);
        float2 p1 = unpack2(acc[i][1]);
        size_t oidx = (((size_t)(n * HH + h) * TT) + t) * HID + m0;
        *reinterpret_cast<float4*>(out + oidx) =
            make_float4(p0.x + bv.x, p0.y + bv.y, p1.x + bv.z, p1.y + bv.w);
    }
}

// ---------------------------------------------------------------------------
// Launch
// ---------------------------------------------------------------------------
extern "C" void kernel_launch(void* const* d_in, const int* in_sizes, int n_in,
                              void* d_out, int out_size) {
    const float* q    = (const float*)d_in[0];
    const float* k    = (const float*)d_in[1];
    const float* v    = (const float*)d_in[2];
    const float* W    = (const float*)d_in[3];
    const float* bias = (const float*)d_in[4];
    float* out = (float*)d_out;

    cudaFuncSetAttribute(chunk_sums_kernel,
                         cudaFuncAttributeMaxDynamicSharedMemorySize, 49152);
    cudaFuncSetAttribute(chunk_out_kernel,
                         cudaFuncAttributeMaxDynamicSharedMemorySize, 101120);

    // probs output (zeros) after context
    if (out_size > CTX_ELEMS) {
        cudaMemsetAsync(out + CTX_ELEMS, 0,
                        (size_t)(out_size - CTX_ELEMS) * sizeof(float), 0);
    }

    sincos_init_kernel<<<4, 256>>>();
    chunk_sums_kernel<<<dim3(NHB, NCH), 256, 49152>>>(k, v);
    prefix_kernel<<<dim3(NHB, NCH), 256>>>();
    chunk_out_kernel<<<dim3(NHB, NCH), 256, 101120>>>(q, k, v);
    outproj_kernel<<<dim3(16, 8), 256>>>(W, bias, out);
}

// round 4
// speedup vs baseline: 1.8677x; 1.0167x over previous
#include <cuda_runtime.h>
#include <cuda_bf16.h>
#include <math.h>

// Problem constants
#define NB   2
#define HH   8
#define TT   1024
#define HID  64
#define NHB  (NB*HH)          // 16 sequences
#define D2   (2*HID)          // 128 expanded feature dim
#define EMB  (HH*HID)         // 512
#define LCH  64               // chunk length
#define NCH  (TT/LCH)         // 16 chunks
#define CTX_ELEMS (NB*HH*TT*HID)  // 1048576
#define ANG_K 0.0015339807878856412f   // (pi/2)/1024

typedef unsigned long long u64t;

__device__ __forceinline__ u64t pack2(float lo, float hi) {
    u64t r; asm("mov.b64 %0, {%1, %2};" : "=l"(r) : "f"(lo), "f"(hi)); return r;
}
__device__ __forceinline__ float2 unpack2(u64t p) {
    float2 r; asm("mov.b64 {%0, %1}, %2;" : "=f"(r.x), "=f"(r.y) : "l"(p)); return r;
}
__device__ __forceinline__ void fma2(u64t& d, u64t a, u64t b) {
    asm("fma.rn.f32x2 %0, %1, %2, %0;" : "+l"(d) : "l"(a), "l"(b));
}
__device__ __forceinline__ void mul2(u64t& d, u64t a, u64t b) {
    asm("mul.rn.f32x2 %0, %1, %2;" : "=l"(d) : "l"(a), "l"(b));
}

// Scratch (device globals; no allocation allowed)
__device__ float g_S   [NHB*NCH*D2*HID];   // chunk sums   [b][c][d][m]
__device__ float g_P   [NHB*NCH*D2*HID];   // excl prefix
__device__ float g_sk  [NHB*NCH*D2];
__device__ float g_skP [NHB*NCH*D2];
__device__ float g_attn[TT*NB*EMB];        // attn in (t, n, e) layout

// ---------------------------------------------------------------------------
// Kernel A: per-(b,chunk) sums  S_c = K_^T V  (128x64),  sk_c = sum_t k_
// Raw K in smem; sin/cos weight folded into the V operand per t.
// grid (16,16), 256 thr, dyn smem = 33280 B
// ---------------------------------------------------------------------------
__global__ __launch_bounds__(256) void chunk_sums_kernel(const float* __restrict__ k,
                                                         const float* __restrict__ v) {
    extern __shared__ float sm[];
    float* sK   = sm;            // [64][64] raw relu K, stride 16 f4
    float* sV   = sm + 4096;     // [64][64]
    float* sSin = sm + 8192;     // [64]
    float* sCos = sm + 8256;     // [64]
    const int b = blockIdx.x, c = blockIdx.y, tid = threadIdx.x;

    if (tid < LCH) {
        float ang = (float)(c * LCH + tid + 1) * ANG_K;
        sSin[tid] = sinf(ang);
        sCos[tid] = cosf(ang);
    }
    const float4* kg = reinterpret_cast<const float4*>(k + ((size_t)b * TT + c * LCH) * HID);
    float4* sK4w = reinterpret_cast<float4*>(sK);
    for (int i = tid; i < LCH * 16; i += 256) {
        float4 kv = kg[i];
        sK4w[i] = make_float4(fmaxf(kv.x, 0.f), fmaxf(kv.y, 0.f),
                              fmaxf(kv.z, 0.f), fmaxf(kv.w, 0.f));
    }
    const float4* vg = reinterpret_cast<const float4*>(v);
    float4* sV4w = reinterpret_cast<float4*>(sV);
    for (int i = tid; i < LCH * 16; i += 256) {
        int t = i >> 4, c4 = i & 15;
        sV4w[t * 16 + c4] = vg[((size_t)(c * LCH + t) * NHB + b) * 16 + c4];
    }
    __syncthreads();

    // expanded d0 = ty*8; weight = (ty<8 ? sin : cos); raw col = (ty&7)*8
    const int tx = tid & 15, ty = tid >> 4;
    const int m0 = tx * 4;
    const float* wT = (ty < 8) ? sSin : sCos;
    u64t acc[8][2];
#pragma unroll
    for (int i = 0; i < 8; ++i) { acc[i][0] = pack2(0.f, 0.f); acc[i][1] = pack2(0.f, 0.f); }

    const float4* sK4 = reinterpret_cast<const float4*>(sK);
    const float4* sV4 = reinterpret_cast<const float4*>(sV);
    for (int t = 0; t < LCH; ++t) {
        float4 a0 = sK4[t * 16 + (ty & 7) * 2];
        float4 a1 = sK4[t * 16 + (ty & 7) * 2 + 1];
        float4 bv = sV4[t * 16 + tx];
        float w = wT[t];
        u64t wp = pack2(w, w);
        u64t b01 = pack2(bv.x, bv.y), b23 = pack2(bv.z, bv.w);
        mul2(b01, b01, wp);
        mul2(b23, b23, wp);
        float av[8] = {a0.x, a0.y, a0.z, a0.w, a1.x, a1.y, a1.z, a1.w};
#pragma unroll
        for (int i = 0; i < 8; ++i) {
            u64t ad = pack2(av[i], av[i]);
            fma2(acc[i][0], ad, b01);
            fma2(acc[i][1], ad, b23);
        }
    }
    float* Sout = g_S + (size_t)(b * NCH + c) * (D2 * HID);
#pragma unroll
    for (int i = 0; i < 8; ++i) {
        float2 p0 = unpack2(acc[i][0]);
        float2 p1 = unpack2(acc[i][1]);
        *reinterpret_cast<float4*>(Sout + (ty * 8 + i) * HID + m0) =
            make_float4(p0.x, p0.y, p1.x, p1.y);
    }

    if (tid < D2) {
        int dl = tid & 63;
        const float* wv = (tid < 64) ? sSin : sCos;
        float s = 0.f;
        for (int t = 0; t < LCH; ++t) s += wv[t] * sK[t * HID + dl];
        g_sk[(b * NCH + c) * D2 + tid] = s;
    }
}

// ---------------------------------------------------------------------------
// Kernel B: exclusive prefix over 16 chunks (per b), grid (16, 16)
// ---------------------------------------------------------------------------
__global__ __launch_bounds__(256) void prefix_kernel() {
    const int b = blockIdx.x, s = blockIdx.y, tid = threadIdx.x;
    size_t eoff = (size_t)s * 512 + tid * 2;
    float r0 = 0.f, r1 = 0.f;
#pragma unroll
    for (int c = 0; c < NCH; ++c) {
        size_t base = (size_t)(b * NCH + c) * (D2 * HID) + eoff;
        float2 sv = *reinterpret_cast<const float2*>(&g_S[base]);
        *reinterpret_cast<float2*>(&g_P[base]) = make_float2(r0, r1);
        r0 += sv.x; r1 += sv.y;
    }
    if (s == 0 && tid < D2) {
        float run = 0.f;
#pragma unroll
        for (int c = 0; c < NCH; ++c) {
            int idx = (b * NCH + c) * D2 + tid;
            g_skP[idx] = run;
            run += g_sk[idx];
        }
    }
}

// ---------------------------------------------------------------------------
// Kernel C: per-(b,chunk) output, L=64, raw 64-dim Q/K + cos(dt) identity
// grid (16,16), 256 thr, dyn smem = 67840 B, 3 CTAs/SM
// ---------------------------------------------------------------------------
__global__ __launch_bounds__(256, 3) void chunk_out_kernel(const float* __restrict__ q,
                                                           const float* __restrict__ k,
                                                           const float* __restrict__ v) {
    extern __shared__ float sm[];
    float* sQ   = sm;            // [64][64] raw relu Q, stride 16 f4    4096
    float* sB   = sm + 4096;     // K raw [64][68] -> P halves [64][68]  4352
    float* sV   = sm + 8448;     // [64][64]                             4096
    float* sS   = sm + 12544;    // [64][64] masked scores               4096
    float* sSin = sm + 16640;    // [64]
    float* sCos = sm + 16704;    // [64]
    float* sSkp = sm + 16768;    // [128]
    float* sDen = sm + 16896;    // [64]

    const int b = blockIdx.x, c = blockIdx.y, tid = threadIdx.x;
    const int lane = tid & 31, w = tid >> 5;

    if (tid < LCH) {
        float ang = (float)(c * LCH + tid + 1) * ANG_K;
        sSin[tid] = sinf(ang);
        sCos[tid] = cosf(ang);
    }
    if (tid < D2) sSkp[tid] = g_skP[(b * NCH + c) * D2 + tid];

    const float4* qg = reinterpret_cast<const float4*>(q + ((size_t)b * TT + c * LCH) * HID);
    const float4* kg = reinterpret_cast<const float4*>(k + ((size_t)b * TT + c * LCH) * HID);
    float4* sQ4w = reinterpret_cast<float4*>(sQ);
    float4* sB4w = reinterpret_cast<float4*>(sB);
    for (int i = tid; i < LCH * 16; i += 256) {
        int t = i >> 4, c4 = i & 15;
        float4 qv = qg[i];
        sQ4w[i] = make_float4(fmaxf(qv.x, 0.f), fmaxf(qv.y, 0.f),
                              fmaxf(qv.z, 0.f), fmaxf(qv.w, 0.f));
        float4 kv = kg[i];
        sB4w[t * 17 + c4] = make_float4(fmaxf(kv.x, 0.f), fmaxf(kv.y, 0.f),
                                        fmaxf(kv.z, 0.f), fmaxf(kv.w, 0.f));
    }
    const float4* vg = reinterpret_cast<const float4*>(v);
    float4* sV4w = reinterpret_cast<float4*>(sV);
    for (int i = tid; i < LCH * 16; i += 256) {
        int t = i >> 4, c4 = i & 15;
        sV4w[t * 16 + c4] = vg[((size_t)(c * LCH + t) * NHB + b) * 16 + c4];
    }
    __syncthreads();

    // ---- scores: 64-dim raw dot * cos(theta_r - theta_tp); warp w rows [8w,8w+8)
    {
        const float4* sQ4 = reinterpret_cast<const float4*>(sQ);
        const float4* sK4 = reinterpret_cast<const float4*>(sB);   // stride 17 f4
        const int r0 = w * 8;
        float acc0[8] = {0,0,0,0,0,0,0,0};
        float acc1[8] = {0,0,0,0,0,0,0,0};
        if (w < 4) {   // rows < 32: cols lane+32 fully masked
            for (int d4 = 0; d4 < 16; ++d4) {
                float4 k0 = sK4[lane * 17 + d4];
#pragma unroll
                for (int i = 0; i < 8; ++i) {
                    float4 qv = sQ4[(r0 + i) * 16 + d4];
                    acc0[i] = fmaf(qv.x, k0.x, acc0[i]);
                    acc0[i] = fmaf(qv.y, k0.y, acc0[i]);
                    acc0[i] = fmaf(qv.z, k0.z, acc0[i]);
                    acc0[i] = fmaf(qv.w, k0.w, acc0[i]);
                }
            }
        } else {
            for (int d4 = 0; d4 < 16; ++d4) {
                float4 k0 = sK4[lane * 17 + d4];
                float4 k1 = sK4[(lane + 32) * 17 + d4];
#pragma unroll
                for (int i = 0; i < 8; ++i) {
                    float4 qv = sQ4[(r0 + i) * 16 + d4];
                    acc0[i] = fmaf(qv.x, k0.x, acc0[i]);
                    acc0[i] = fmaf(qv.y, k0.y, acc0[i]);
                    acc0[i] = fmaf(qv.z, k0.z, acc0[i]);
                    acc0[i] = fmaf(qv.w, k0.w, acc0[i]);
                    acc1[i] = fmaf(qv.x, k1.x, acc1[i]);
                    acc1[i] = fmaf(qv.y, k1.y, acc1[i]);
                    acc1[i] = fmaf(qv.z, k1.z, acc1[i]);
                    acc1[i] = fmaf(qv.w, k1.w, acc1[i]);
                }
            }
        }
        float sk0 = sSin[lane], ck0 = sCos[lane];
        float sk1 = sSin[lane + 32], ck1 = sCos[lane + 32];
#pragma unroll
        for (int i = 0; i < 8; ++i) {
            int r = r0 + i;
            float sr = sSin[r], cr = sCos[r];
            float f0 = cr * ck0 + sr * sk0;            // cos(theta_r - theta_l)
            float f1 = cr * ck1 + sr * sk1;
            float v0 = (lane <= r)      ? acc0[i] * f0 : 0.f;
            float v1 = (lane + 32 <= r) ? acc1[i] * f1 : 0.f;
            sS[r * LCH + lane]      = v0;
            sS[r * LCH + lane + 32] = v1;
            // denominator: q_.skP = sr*(qr.skp[0:64]) + cr*(qr.skp[64:128])
            float qra = sQ[r * HID + lane];
            float qrb = sQ[r * HID + lane + 32];
            float pl = sr * (qra * sSkp[lane] + qrb * sSkp[lane + 32])
                     + cr * (qra * sSkp[64 + lane] + qrb * sSkp[96 + lane]);
            float p = v0 + v1 + pl;
#pragma unroll
            for (int o = 16; o > 0; o >>= 1) p += __shfl_xor_sync(0xFFFFFFFFu, p, o);
            if (lane == 0) sDen[r] = fmaxf(p, 1e-6f);
        }
    }
    __syncthreads();

    // ---- O phase: accS = S@V; then two P-half passes folded in with row scales
    {
        const int tx = tid & 15, ty = tid >> 4;
        const int r0 = ty * 4, m0 = tx * 4;
        const float4* sQ4 = reinterpret_cast<const float4*>(sQ);
        const float4* sS4 = reinterpret_cast<const float4*>(sS);
        const float4* sV4 = reinterpret_cast<const float4*>(sV);
        const float4* sP4 = reinterpret_cast<const float4*>(sB);   // stride 17 f4
        const float4* Pg  = reinterpret_cast<const float4*>(
                                g_P + (size_t)(b * NCH + c) * (D2 * HID));
        float4* sPw = reinterpret_cast<float4*>(sB);

        u64t accS[4][2], accT[4][2];
#pragma unroll
        for (int i = 0; i < 4; ++i) { accS[i][0] = pack2(0.f,0.f); accS[i][1] = pack2(0.f,0.f); }

        // S @ V
        for (int tp4 = 0; tp4 < 16; ++tp4) {
            float4 a[4];
#pragma unroll
            for (int i = 0; i < 4; ++i) a[i] = sS4[(r0 + i) * 16 + tp4];
            float4 b0 = sV4[(4 * tp4 + 0) * 16 + tx];
            float4 b1 = sV4[(4 * tp4 + 1) * 16 + tx];
            float4 b2 = sV4[(4 * tp4 + 2) * 16 + tx];
            float4 b3 = sV4[(4 * tp4 + 3) * 16 + tx];
            u64t b0l = pack2(b0.x,b0.y), b0h = pack2(b0.z,b0.w);
            u64t b1l = pack2(b1.x,b1.y), b1h = pack2(b1.z,b1.w);
            u64t b2l = pack2(b2.x,b2.y), b2h = pack2(b2.z,b2.w);
            u64t b3l = pack2(b3.x,b3.y), b3h = pack2(b3.z,b3.w);
#pragma unroll
            for (int i = 0; i < 4; ++i) {
                u64t ax = pack2(a[i].x, a[i].x); fma2(accS[i][0], ax, b0l); fma2(accS[i][1], ax, b0h);
                u64t ay = pack2(a[i].y, a[i].y); fma2(accS[i][0], ay, b1l); fma2(accS[i][1], ay, b1h);
                u64t az = pack2(a[i].z, a[i].z); fma2(accS[i][0], az, b2l); fma2(accS[i][1], az, b2h);
                u64t aw = pack2(a[i].w, a[i].w); fma2(accS[i][0], aw, b3l); fma2(accS[i][1], aw, b3h);
            }
        }
        __syncthreads();   // all reads of K (sB) finished earlier; scores done

        // two passes: half = 0 (sin rows of P), half = 1 (cos rows)
#pragma unroll
        for (int half = 0; half < 2; ++half) {
            for (int i = tid; i < 1024; i += 256) {     // stage 64x64 P half
                int row = i >> 4, c4 = i & 15;
                sPw[row * 17 + c4] = Pg[half * 1024 + i];
            }
            __syncthreads();
#pragma unroll
            for (int i = 0; i < 4; ++i) { accT[i][0] = pack2(0.f,0.f); accT[i][1] = pack2(0.f,0.f); }
            for (int d4 = 0; d4 < 16; ++d4) {
                float4 a[4];
#pragma unroll
                for (int i = 0; i < 4; ++i) a[i] = sQ4[(r0 + i) * 16 + d4];
                float4 b0 = sP4[(4 * d4 + 0) * 17 + tx];
                float4 b1 = sP4[(4 * d4 + 1) * 17 + tx];
                float4 b2 = sP4[(4 * d4 + 2) * 17 + tx];
                float4 b3 = sP4[(4 * d4 + 3) * 17 + tx];
                u64t b0l = pack2(b0.x,b0.y), b0h = pack2(b0.z,b0.w);
                u64t b1l = pack2(b1.x,b1.y), b1h = pack2(b1.z,b1.w);
                u64t b2l = pack2(b2.x,b2.y), b2h = pack2(b2.z,b2.w);
                u64t b3l = pack2(b3.x,b3.y), b3h = pack2(b3.z,b3.w);
#pragma unroll
                for (int i = 0; i < 4; ++i) {
                    u64t ax = pack2(a[i].x, a[i].x); fma2(accT[i][0], ax, b0l); fma2(accT[i][1], ax, b0h);
                    u64t ay = pack2(a[i].y, a[i].y); fma2(accT[i][0], ay, b1l); fma2(accT[i][1], ay, b1h);
                    u64t az = pack2(a[i].z, a[i].z); fma2(accT[i][0], az, b2l); fma2(accT[i][1], az, b2h);
                    u64t aw = pack2(a[i].w, a[i].w); fma2(accT[i][0], aw, b3l); fma2(accT[i][1], aw, b3h);
                }
            }
            const float* wT = half ? sCos : sSin;
#pragma unroll
            for (int i = 0; i < 4; ++i) {
                float wv = wT[r0 + i];
                u64t wd = pack2(wv, wv);
                fma2(accS[i][0], wd, accT[i][0]);
                fma2(accS[i][1], wd, accT[i][1]);
            }
            if (half == 0) __syncthreads();  // before overwriting sB with cos half
        }

        const int n = b >> 3, h = b & 7;
#pragma unroll
        for (int i = 0; i < 4; ++i) {
            int r = r0 + i;
            float inv = 1.0f / sDen[r];
            float2 p0 = unpack2(accS[i][0]);
            float2 p1 = unpack2(accS[i][1]);
            int tg = c * LCH + r;
            *reinterpret_cast<float4*>(g_attn + ((size_t)tg * NB + n) * EMB + h * HID + m0) =
                make_float4(p0.x * inv, p0.y * inv, p1.x * inv, p1.y * inv);
        }
    }
}

// ---------------------------------------------------------------------------
// Kernel D: out = attn @ W^T + b, scattered to context (N,H,T,HID)
// grid (16,8), 256 thr, 128x64 tiles, k-tile 32, 8x4/thread, f32x2
// ---------------------------------------------------------------------------
#define SB_STRIDE 72
__global__ __launch_bounds__(256) void outproj_kernel(const float* __restrict__ W,
                                                      const float* __restrict__ bias,
                                                      float* __restrict__ out) {
    __shared__ float sA[32 * 137];
    __shared__ float sB[32 * SB_STRIDE];

    const int tid = threadIdx.x;
    const int rb = blockIdx.x * 128;
    const int nb = blockIdx.y * 64;
    const int tx = tid & 15, ty = tid >> 4;
    const int r0 = ty * 8, m0 = tx * 4;

    u64t acc[8][2];
#pragma unroll
    for (int i = 0; i < 8; ++i) { acc[i][0] = pack2(0.f,0.f); acc[i][1] = pack2(0.f,0.f); }

    const float4* Ag = reinterpret_cast<const float4*>(g_attn);
    const float4* Wg = reinterpret_cast<const float4*>(W);

    for (int k0 = 0; k0 < EMB; k0 += 32) {
        for (int i = tid; i < 1024; i += 256) {
            int r = i >> 3, k4 = i & 7;
            float4 a = Ag[(size_t)(rb + r) * (EMB / 4) + (k0 >> 2) + k4];
            sA[(k4 * 4 + 0) * 137 + r] = a.x;
            sA[(k4 * 4 + 1) * 137 + r] = a.y;
            sA[(k4 * 4 + 2) * 137 + r] = a.z;
            sA[(k4 * 4 + 3) * 137 + r] = a.w;
        }
        for (int i = tid; i < 512; i += 256) {
            int n = i >> 3, k4 = i & 7;
            float4 wv = Wg[(size_t)(nb + n) * (EMB / 4) + (k0 >> 2) + k4];
            sB[(k4 * 4 + 0) * SB_STRIDE + n] = wv.x;
            sB[(k4 * 4 + 1) * SB_STRIDE + n] = wv.y;
            sB[(k4 * 4 + 2) * SB_STRIDE + n] = wv.z;
            sB[(k4 * 4 + 3) * SB_STRIDE + n] = wv.w;
        }
        __syncthreads();
#pragma unroll 8
        for (int kk = 0; kk < 32; ++kk) {
            float2 bl = *reinterpret_cast<const float2*>(&sB[kk * SB_STRIDE + m0]);
            float2 bh = *reinterpret_cast<const float2*>(&sB[kk * SB_STRIDE + m0 + 2]);
            u64t b0 = pack2(bl.x, bl.y), b1 = pack2(bh.x, bh.y);
            const float* arow = &sA[kk * 137 + r0];
#pragma unroll
            for (int i = 0; i < 8; ++i) {
                float a = arow[i];
                u64t ad = pack2(a, a);
                fma2(acc[i][0], ad, b0);
                fma2(acc[i][1], ad, b1);
            }
        }
        __syncthreads();
    }

    float4 bv = *reinterpret_cast<const float4*>(&bias[nb + m0]);
    const int h = nb >> 6;
#pragma unroll
    for (int i = 0; i < 8; ++i) {
        int r = rb + r0 + i;
        int t = r >> 1, n = r & 1;
        float2 p0 = unpack2(acc[i][0]);
        float2 p1 = unpack2(acc[i][1]);
        size_t oidx = (((size_t)(n * HH + h) * TT) + t) * HID + m0;
        *reinterpret_cast<float4*>(out + oidx) =
            make_float4(p0.x + bv.x, p0.y + bv.y, p1.x + bv.z, p1.y + bv.w);
    }
}

// ---------------------------------------------------------------------------
// Launch: fork probs-memset onto a side stream (capture-legal event fork/join)
// ---------------------------------------------------------------------------
extern "C" void kernel_launch(void* const* d_in, const int* in_sizes, int n_in,
                              void* d_out, int out_size) {
    const float* q    = (const float*)d_in[0];
    const float* k    = (const float*)d_in[1];
    const float* v    = (const float*)d_in[2];
    const float* W    = (const float*)d_in[3];
    const float* bias = (const float*)d_in[4];
    float* out = (float*)d_out;

    static cudaStream_t s_side = nullptr;
    static cudaEvent_t evF = nullptr, evJ = nullptr;
    if (!s_side) {
        cudaStreamCreateWithFlags(&s_side, cudaStreamNonBlocking);
        cudaEventCreateWithFlags(&evF, cudaEventDisableTiming);
        cudaEventCreateWithFlags(&evJ, cudaEventDisableTiming);
    }

    cudaFuncSetAttribute(chunk_out_kernel,
                         cudaFuncAttributeMaxDynamicSharedMemorySize, 67840);

    const bool has_probs = (out_size > CTX_ELEMS);
    if (has_probs) {
        cudaEventRecord(evF, 0);
        cudaStreamWaitEvent(s_side, evF, 0);
        cudaMemsetAsync(out + CTX_ELEMS, 0,
                        (size_t)(out_size - CTX_ELEMS) * sizeof(float), s_side);
        cudaEventRecord(evJ, s_side);
    }

    chunk_sums_kernel<<<dim3(NHB, NCH), 256, 33280>>>(k, v);
    prefix_kernel<<<dim3(NHB, NCH), 256>>>();
    chunk_out_kernel<<<dim3(NHB, NCH), 256, 67840>>>(q, k, v);
    outproj_kernel<<<dim3(16, 8), 256>>>(W, bias, out);

    if (has_probs) cudaStreamWaitEvent(0, evJ, 0);
}

// round 5
// speedup vs baseline: 2.5030x; 1.3402x over previous
#include <cuda_runtime.h>
#include <cuda_bf16.h>
#include <math.h>

// Problem constants
#define NB   2
#define HH   8
#define TT   1024
#define HID  64
#define NHB  (NB*HH)          // 16 sequences
#define D2   (2*HID)          // 128 expanded feature dim
#define EMB  (HH*HID)         // 512
#define LCH  64               // chunk length
#define NCH  (TT/LCH)         // 16 chunks
#define CTX_ELEMS (NB*HH*TT*HID)  // 1048576
#define ANG_K 0.0015339807878856412f   // (pi/2)/1024

typedef unsigned long long u64t;

__device__ __forceinline__ u64t pack2(float lo, float hi) {
    u64t r; asm("mov.b64 %0, {%1, %2};" : "=l"(r) : "f"(lo), "f"(hi)); return r;
}
__device__ __forceinline__ float2 unpack2(u64t p) {
    float2 r; asm("mov.b64 {%0, %1}, %2;" : "=f"(r.x), "=f"(r.y) : "l"(p)); return r;
}
__device__ __forceinline__ void fma2(u64t& d, u64t a, u64t b) {
    asm("fma.rn.f32x2 %0, %1, %2, %0;" : "+l"(d) : "l"(a), "l"(b));
}
__device__ __forceinline__ void mul2(u64t& d, u64t a, u64t b) {
    asm("mul.rn.f32x2 %0, %1, %2;" : "=l"(d) : "l"(a), "l"(b));
}

// Scratch (device globals; no allocation allowed)
__device__ float g_S   [NHB*NCH*D2*HID];
__device__ float g_P   [NHB*NCH*D2*HID];
__device__ float g_sk  [NHB*NCH*D2];
__device__ float g_skP [NHB*NCH*D2];
__device__ float g_attn[TT*NB*EMB];

// ---------------------------------------------------------------------------
// Kernel A: per-(b,chunk) sums  S_c = K_^T V,  sk_c = sum_t k_
// ---------------------------------------------------------------------------
__global__ __launch_bounds__(256) void chunk_sums_kernel(const float* __restrict__ k,
                                                         const float* __restrict__ v) {
    extern __shared__ float sm[];
    float* sK   = sm;            // [64][64] raw relu K
    float* sV   = sm + 4096;     // [64][64]
    float* sSin = sm + 8192;     // [64]
    float* sCos = sm + 8256;     // [64]
    const int b = blockIdx.x, c = blockIdx.y, tid = threadIdx.x;

    if (tid < LCH) {
        float ang = (float)(c * LCH + tid + 1) * ANG_K;
        sSin[tid] = sinf(ang);
        sCos[tid] = cosf(ang);
    }
    const float4* kg = reinterpret_cast<const float4*>(k + ((size_t)b * TT + c * LCH) * HID);
    float4* sK4w = reinterpret_cast<float4*>(sK);
    for (int i = tid; i < LCH * 16; i += 256) {
        float4 kv = kg[i];
        sK4w[i] = make_float4(fmaxf(kv.x, 0.f), fmaxf(kv.y, 0.f),
                              fmaxf(kv.z, 0.f), fmaxf(kv.w, 0.f));
    }
    const float4* vg = reinterpret_cast<const float4*>(v);
    float4* sV4w = reinterpret_cast<float4*>(sV);
    for (int i = tid; i < LCH * 16; i += 256) {
        int t = i >> 4, c4 = i & 15;
        sV4w[t * 16 + c4] = vg[((size_t)(c * LCH + t) * NHB + b) * 16 + c4];
    }
    __syncthreads();

    const int tx = tid & 15, ty = tid >> 4;
    const int m0 = tx * 4;
    const float* wT = (ty < 8) ? sSin : sCos;
    u64t acc[8][2];
#pragma unroll
    for (int i = 0; i < 8; ++i) { acc[i][0] = pack2(0.f, 0.f); acc[i][1] = pack2(0.f, 0.f); }

    const float4* sK4 = reinterpret_cast<const float4*>(sK);
    const float4* sV4 = reinterpret_cast<const float4*>(sV);
    for (int t = 0; t < LCH; ++t) {
        float4 a0 = sK4[t * 16 + (ty & 7) * 2];
        float4 a1 = sK4[t * 16 + (ty & 7) * 2 + 1];
        float4 bv = sV4[t * 16 + tx];
        float w = wT[t];
        u64t wp = pack2(w, w);
        u64t b01 = pack2(bv.x, bv.y), b23 = pack2(bv.z, bv.w);
        mul2(b01, b01, wp);
        mul2(b23, b23, wp);
        float av[8] = {a0.x, a0.y, a0.z, a0.w, a1.x, a1.y, a1.z, a1.w};
#pragma unroll
        for (int i = 0; i < 8; ++i) {
            u64t ad = pack2(av[i], av[i]);
            fma2(acc[i][0], ad, b01);
            fma2(acc[i][1], ad, b23);
        }
    }
    float* Sout = g_S + (size_t)(b * NCH + c) * (D2 * HID);
#pragma unroll
    for (int i = 0; i < 8; ++i) {
        float2 p0 = unpack2(acc[i][0]);
        float2 p1 = unpack2(acc[i][1]);
        *reinterpret_cast<float4*>(Sout + (ty * 8 + i) * HID + m0) =
            make_float4(p0.x, p0.y, p1.x, p1.y);
    }

    if (tid < D2) {
        int dl = tid & 63;
        const float* wv = (tid < 64) ? sSin : sCos;
        float s = 0.f;
        for (int t = 0; t < LCH; ++t) s += wv[t] * sK[t * HID + dl];
        g_sk[(b * NCH + c) * D2 + tid] = s;
    }
}

// ---------------------------------------------------------------------------
// Kernel B: exclusive prefix over 16 chunks (per b), grid (16, 16)
// ---------------------------------------------------------------------------
__global__ __launch_bounds__(256) void prefix_kernel() {
    const int b = blockIdx.x, s = blockIdx.y, tid = threadIdx.x;
    size_t eoff = (size_t)s * 512 + tid * 2;
    float r0 = 0.f, r1 = 0.f;
#pragma unroll
    for (int c = 0; c < NCH; ++c) {
        size_t base = (size_t)(b * NCH + c) * (D2 * HID) + eoff;
        float2 sv = *reinterpret_cast<const float2*>(&g_S[base]);
        *reinterpret_cast<float2*>(&g_P[base]) = make_float2(r0, r1);
        r0 += sv.x; r1 += sv.y;
    }
    if (s == 0 && tid < D2) {
        float run = 0.f;
#pragma unroll
        for (int c = 0; c < NCH; ++c) {
            int idx = (b * NCH + c) * D2 + tid;
            g_skP[idx] = run;
            run += g_sk[idx];
        }
    }
}

// ---------------------------------------------------------------------------
// Kernel C: per-(b,chunk) output, L=64, raw 64-dim Q/K + cos(dt) identity
// ---------------------------------------------------------------------------
__global__ __launch_bounds__(256, 3) void chunk_out_kernel(const float* __restrict__ q,
                                                           const float* __restrict__ k,
                                                           const float* __restrict__ v) {
    extern __shared__ float sm[];
    float* sQ   = sm;            // [64][64]
    float* sB   = sm + 4096;     // K raw [64][68] -> P halves
    float* sV   = sm + 8448;     // [64][64]
    float* sS   = sm + 12544;    // [64][64]
    float* sSin = sm + 16640;
    float* sCos = sm + 16704;
    float* sSkp = sm + 16768;
    float* sDen = sm + 16896;

    const int b = blockIdx.x, c = blockIdx.y, tid = threadIdx.x;
    const int lane = tid & 31, w = tid >> 5;

    if (tid < LCH) {
        float ang = (float)(c * LCH + tid + 1) * ANG_K;
        sSin[tid] = sinf(ang);
        sCos[tid] = cosf(ang);
    }
    if (tid < D2) sSkp[tid] = g_skP[(b * NCH + c) * D2 + tid];

    const float4* qg = reinterpret_cast<const float4*>(q + ((size_t)b * TT + c * LCH) * HID);
    const float4* kg = reinterpret_cast<const float4*>(k + ((size_t)b * TT + c * LCH) * HID);
    float4* sQ4w = reinterpret_cast<float4*>(sQ);
    float4* sB4w = reinterpret_cast<float4*>(sB);
    for (int i = tid; i < LCH * 16; i += 256) {
        int t = i >> 4, c4 = i & 15;
        float4 qv = qg[i];
        sQ4w[i] = make_float4(fmaxf(qv.x, 0.f), fmaxf(qv.y, 0.f),
                              fmaxf(qv.z, 0.f), fmaxf(qv.w, 0.f));
        float4 kv = kg[i];
        sB4w[t * 17 + c4] = make_float4(fmaxf(kv.x, 0.f), fmaxf(kv.y, 0.f),
                                        fmaxf(kv.z, 0.f), fmaxf(kv.w, 0.f));
    }
    const float4* vg = reinterpret_cast<const float4*>(v);
    float4* sV4w = reinterpret_cast<float4*>(sV);
    for (int i = tid; i < LCH * 16; i += 256) {
        int t = i >> 4, c4 = i & 15;
        sV4w[t * 16 + c4] = vg[((size_t)(c * LCH + t) * NHB + b) * 16 + c4];
    }
    __syncthreads();

    {
        const float4* sQ4 = reinterpret_cast<const float4*>(sQ);
        const float4* sK4 = reinterpret_cast<const float4*>(sB);
        const int r0 = w * 8;
        float acc0[8] = {0,0,0,0,0,0,0,0};
        float acc1[8] = {0,0,0,0,0,0,0,0};
        if (w < 4) {
            for (int d4 = 0; d4 < 16; ++d4) {
                float4 k0 = sK4[lane * 17 + d4];
#pragma unroll
                for (int i = 0; i < 8; ++i) {
                    float4 qv = sQ4[(r0 + i) * 16 + d4];
                    acc0[i] = fmaf(qv.x, k0.x, acc0[i]);
                    acc0[i] = fmaf(qv.y, k0.y, acc0[i]);
                    acc0[i] = fmaf(qv.z, k0.z, acc0[i]);
                    acc0[i] = fmaf(qv.w, k0.w, acc0[i]);
                }
            }
        } else {
            for (int d4 = 0; d4 < 16; ++d4) {
                float4 k0 = sK4[lane * 17 + d4];
                float4 k1 = sK4[(lane + 32) * 17 + d4];
#pragma unroll
                for (int i = 0; i < 8; ++i) {
                    float4 qv = sQ4[(r0 + i) * 16 + d4];
                    acc0[i] = fmaf(qv.x, k0.x, acc0[i]);
                    acc0[i] = fmaf(qv.y, k0.y, acc0[i]);
                    acc0[i] = fmaf(qv.z, k0.z, acc0[i]);
                    acc0[i] = fmaf(qv.w, k0.w, acc0[i]);
                    acc1[i] = fmaf(qv.x, k1.x, acc1[i]);
                    acc1[i] = fmaf(qv.y, k1.y, acc1[i]);
                    acc1[i] = fmaf(qv.z, k1.z, acc1[i]);
                    acc1[i] = fmaf(qv.w, k1.w, acc1[i]);
                }
            }
        }
        float sk0 = sSin[lane], ck0 = sCos[lane];
        float sk1 = sSin[lane + 32], ck1 = sCos[lane + 32];
#pragma unroll
        for (int i = 0; i < 8; ++i) {
            int r = r0 + i;
            float sr = sSin[r], cr = sCos[r];
            float f0 = cr * ck0 + sr * sk0;
            float f1 = cr * ck1 + sr * sk1;
            float v0 = (lane <= r)      ? acc0[i] * f0 : 0.f;
            float v1 = (lane + 32 <= r) ? acc1[i] * f1 : 0.f;
            sS[r * LCH + lane]      = v0;
            sS[r * LCH + lane + 32] = v1;
            float qra = sQ[r * HID + lane];
            float qrb = sQ[r * HID + lane + 32];
            float pl = sr * (qra * sSkp[lane] + qrb * sSkp[lane + 32])
                     + cr * (qra * sSkp[64 + lane] + qrb * sSkp[96 + lane]);
            float p = v0 + v1 + pl;
#pragma unroll
            for (int o = 16; o > 0; o >>= 1) p += __shfl_xor_sync(0xFFFFFFFFu, p, o);
            if (lane == 0) sDen[r] = fmaxf(p, 1e-6f);
        }
    }
    __syncthreads();

    {
        const int tx = tid & 15, ty = tid >> 4;
        const int r0 = ty * 4, m0 = tx * 4;
        const float4* sQ4 = reinterpret_cast<const float4*>(sQ);
        const float4* sS4 = reinterpret_cast<const float4*>(sS);
        const float4* sV4 = reinterpret_cast<const float4*>(sV);
        const float4* sP4 = reinterpret_cast<const float4*>(sB);
        const float4* Pg  = reinterpret_cast<const float4*>(
                                g_P + (size_t)(b * NCH + c) * (D2 * HID));
        float4* sPw = reinterpret_cast<float4*>(sB);

        u64t accS[4][2], accT[4][2];
#pragma unroll
        for (int i = 0; i < 4; ++i) { accS[i][0] = pack2(0.f,0.f); accS[i][1] = pack2(0.f,0.f); }

        for (int tp4 = 0; tp4 < 16; ++tp4) {
            float4 a[4];
#pragma unroll
            for (int i = 0; i < 4; ++i) a[i] = sS4[(r0 + i) * 16 + tp4];
            float4 b0 = sV4[(4 * tp4 + 0) * 16 + tx];
            float4 b1 = sV4[(4 * tp4 + 1) * 16 + tx];
            float4 b2 = sV4[(4 * tp4 + 2) * 16 + tx];
            float4 b3 = sV4[(4 * tp4 + 3) * 16 + tx];
            u64t b0l = pack2(b0.x,b0.y), b0h = pack2(b0.z,b0.w);
            u64t b1l = pack2(b1.x,b1.y), b1h = pack2(b1.z,b1.w);
            u64t b2l = pack2(b2.x,b2.y), b2h = pack2(b2.z,b2.w);
            u64t b3l = pack2(b3.x,b3.y), b3h = pack2(b3.z,b3.w);
#pragma unroll
            for (int i = 0; i < 4; ++i) {
                u64t ax = pack2(a[i].x, a[i].x); fma2(accS[i][0], ax, b0l); fma2(accS[i][1], ax, b0h);
                u64t ay = pack2(a[i].y, a[i].y); fma2(accS[i][0], ay, b1l); fma2(accS[i][1], ay, b1h);
                u64t az = pack2(a[i].z, a[i].z); fma2(accS[i][0], az, b2l); fma2(accS[i][1], az, b2h);
                u64t aw = pack2(a[i].w, a[i].w); fma2(accS[i][0], aw, b3l); fma2(accS[i][1], aw, b3h);
            }
        }
        __syncthreads();

#pragma unroll
        for (int half = 0; half < 2; ++half) {
            for (int i = tid; i < 1024; i += 256) {
                int row = i >> 4, c4 = i & 15;
                sPw[row * 17 + c4] = Pg[half * 1024 + i];
            }
            __syncthreads();
#pragma unroll
            for (int i = 0; i < 4; ++i) { accT[i][0] = pack2(0.f,0.f); accT[i][1] = pack2(0.f,0.f); }
            for (int d4 = 0; d4 < 16; ++d4) {
                float4 a[4];
#pragma unroll
                for (int i = 0; i < 4; ++i) a[i] = sQ4[(r0 + i) * 16 + d4];
                float4 b0 = sP4[(4 * d4 + 0) * 17 + tx];
                float4 b1 = sP4[(4 * d4 + 1) * 17 + tx];
                float4 b2 = sP4[(4 * d4 + 2) * 17 + tx];
                float4 b3 = sP4[(4 * d4 + 3) * 17 + tx];
                u64t b0l = pack2(b0.x,b0.y), b0h = pack2(b0.z,b0.w);
                u64t b1l = pack2(b1.x,b1.y), b1h = pack2(b1.z,b1.w);
                u64t b2l = pack2(b2.x,b2.y), b2h = pack2(b2.z,b2.w);
                u64t b3l = pack2(b3.x,b3.y), b3h = pack2(b3.z,b3.w);
#pragma unroll
                for (int i = 0; i < 4; ++i) {
                    u64t ax = pack2(a[i].x, a[i].x); fma2(accT[i][0], ax, b0l); fma2(accT[i][1], ax, b0h);
                    u64t ay = pack2(a[i].y, a[i].y); fma2(accT[i][0], ay, b1l); fma2(accT[i][1], ay, b1h);
                    u64t az = pack2(a[i].z, a[i].z); fma2(accT[i][0], az, b2l); fma2(accT[i][1], az, b2h);
                    u64t aw = pack2(a[i].w, a[i].w); fma2(accT[i][0], aw, b3l); fma2(accT[i][1], aw, b3h);
                }
            }
            const float* wT = half ? sCos : sSin;
#pragma unroll
            for (int i = 0; i < 4; ++i) {
                float wv = wT[r0 + i];
                u64t wd = pack2(wv, wv);
                fma2(accS[i][0], wd, accT[i][0]);
                fma2(accS[i][1], wd, accT[i][1]);
            }
            if (half == 0) __syncthreads();
        }

        const int n = b >> 3, h = b & 7;
#pragma unroll
        for (int i = 0; i < 4; ++i) {
            int r = r0 + i;
            float inv = 1.0f / sDen[r];
            float2 p0 = unpack2(accS[i][0]);
            float2 p1 = unpack2(accS[i][1]);
            int tg = c * LCH + r;
            *reinterpret_cast<float4*>(g_attn + ((size_t)tg * NB + n) * EMB + h * HID + m0) =
                make_float4(p0.x * inv, p0.y * inv, p1.x * inv, p1.y * inv);
        }
    }
}

// ---------------------------------------------------------------------------
// Kernel D v2: out = attn @ W^T + b
// grid (32,8) = 256 CTAs, 128 threads, 64x64 tiles, k-tile 64, 8x4/thread
// XOR-swizzled transposed smem tiles, double-buffered, f32x2 FMAs
// ---------------------------------------------------------------------------
__global__ __launch_bounds__(128) void outproj_kernel(const float* __restrict__ W,
                                                      const float* __restrict__ bias,
                                                      float* __restrict__ out) {
    extern __shared__ float sm[];
    // [2 buffers][ A:64x64 | B:64x64 ] floats = 65536 B
    const int tid = threadIdx.x;
    const int rb = blockIdx.x * 64;
    const int nb = blockIdx.y * 64;
    const int tx = tid & 15, ty = tid >> 4;   // ty 0..7
    const int r0 = ty * 8, m0 = tx * 4;

    const float4* Ag = reinterpret_cast<const float4*>(g_attn) + (size_t)rb * 128;
    const float4* Wg = reinterpret_cast<const float4*>(W) + (size_t)nb * 128;

    u64t acc[8][2];
#pragma unroll
    for (int i = 0; i < 8; ++i) { acc[i][0] = pack2(0.f,0.f); acc[i][1] = pack2(0.f,0.f); }

    float4 ra[8], rw[8];

    // global load of k-tile kt into registers (coalesced: k4 fastest)
    auto loadG = [&](int kt) {
        const int kb = kt * 16;
#pragma unroll
        for (int j = 0; j < 8; ++j) {
            int i = tid + j * 128;
            int row = i >> 4, k4 = i & 15;
            ra[j] = Ag[(size_t)row * 128 + kb + k4];
            rw[j] = Wg[(size_t)row * 128 + kb + k4];
        }
    };
    // transposed + XOR-swizzled store: element q -> kk = k4*4+q,
    // col = (row&3) + 4*((row>>2) ^ (kk>>2));  kk>>2 == k4
    auto storeT = [&](float* sA, float* sB) {
#pragma unroll
        for (int j = 0; j < 8; ++j) {
            int i = tid + j * 128;
            int row = i >> 4, k4 = i & 15;
            int col = (row & 3) + 4 * ((row >> 2) ^ k4);
#pragma unroll
            for (int qq = 0; qq < 4; ++qq) {
                int kk = k4 * 4 + qq;
                sA[kk * 64 + col] = (&ra[j].x)[qq];
                sB[kk * 64 + col] = (&rw[j].x)[qq];
            }
        }
    };
    auto compute = [&](const float* sA, const float* sB) {
        const float4* sA4 = reinterpret_cast<const float4*>(sA);
        const float4* sB4 = reinterpret_cast<const float4*>(sB);
#pragma unroll 8
        for (int kk = 0; kk < 64; ++kk) {
            int s = kk >> 2;
            float4 b4 = sB4[kk * 16 + (tx ^ s)];
            float4 a0 = sA4[kk * 16 + ((2 * ty) ^ s)];
            float4 a1 = sA4[kk * 16 + ((2 * ty + 1) ^ s)];
            u64t b01 = pack2(b4.x, b4.y), b23 = pack2(b4.z, b4.w);
            float av[8] = {a0.x, a0.y, a0.z, a0.w, a1.x, a1.y, a1.z, a1.w};
#pragma unroll
            for (int i = 0; i < 8; ++i) {
                u64t ad = pack2(av[i], av[i]);
                fma2(acc[i][0], ad, b01);
                fma2(acc[i][1], ad, b23);
            }
        }
    };

    loadG(0);
    storeT(sm, sm + 4096);
    __syncthreads();
#pragma unroll
    for (int kt = 0; kt < 8; ++kt) {
        float* base = sm + (kt & 1) * 8192;
        if (kt < 7) loadG(kt + 1);
        compute(base, base + 4096);
        if (kt < 7) {
            float* nxt = sm + ((kt + 1) & 1) * 8192;
            storeT(nxt, nxt + 4096);
            __syncthreads();
        }
    }

    float4 bv = *reinterpret_cast<const float4*>(&bias[nb + m0]);
    const int h = nb >> 6;
#pragma unroll
    for (int i = 0; i < 8; ++i) {
        int r = rb + r0 + i;
        int t = r >> 1, n = r & 1;
        float2 p0 = unpack2(acc[i][0]);
        float2 p1 = unpack2(acc[i][1]);
        size_t oidx = (((size_t)(n * HH + h) * TT) + t) * HID + m0;
        *reinterpret_cast<float4*>(out + oidx) =
            make_float4(p0.x + bv.x, p0.y + bv.y, p1.x + bv.z, p1.y + bv.w);
    }
}

// ---------------------------------------------------------------------------
// Launch
// ---------------------------------------------------------------------------
extern "C" void kernel_launch(void* const* d_in, const int* in_sizes, int n_in,
                              void* d_out, int out_size) {
    const float* q    = (const float*)d_in[0];
    const float* k    = (const float*)d_in[1];
    const float* v    = (const float*)d_in[2];
    const float* W    = (const float*)d_in[3];
    const float* bias = (const float*)d_in[4];
    float* out = (float*)d_out;

    static cudaStream_t s_side = nullptr;
    static cudaEvent_t evF = nullptr, evJ = nullptr;
    if (!s_side) {
        cudaStreamCreateWithFlags(&s_side, cudaStreamNonBlocking);
        cudaEventCreateWithFlags(&evF, cudaEventDisableTiming);
        cudaEventCreateWithFlags(&evJ, cudaEventDisableTiming);
    }

    cudaFuncSetAttribute(chunk_out_kernel,
                         cudaFuncAttributeMaxDynamicSharedMemorySize, 67840);
    cudaFuncSetAttribute(outproj_kernel,
                         cudaFuncAttributeMaxDynamicSharedMemorySize, 65536);

    const bool has_probs = (out_size > CTX_ELEMS);
    if (has_probs) {
        cudaEventRecord(evF, 0);
        cudaStreamWaitEvent(s_side, evF, 0);
        cudaMemsetAsync(out + CTX_ELEMS, 0,
                        (size_t)(out_size - CTX_ELEMS) * sizeof(float), s_side);
        cudaEventRecord(evJ, s_side);
    }

    chunk_sums_kernel<<<dim3(NHB, NCH), 256, 33280>>>(k, v);
    prefix_kernel<<<dim3(NHB, NCH), 256>>>();
    chunk_out_kernel<<<dim3(NHB, NCH), 256, 67840>>>(q, k, v);
    outproj_kernel<<<dim3(32, 8), 128, 65536>>>(W, bias, out);

    if (has_probs) cudaStreamWaitEvent(0, evJ, 0);
}